// round 10
// baseline (speedup 1.0000x reference)
#include <cuda_runtime.h>
#include <cuda_fp16.h>

#define EMBED_DIM   256
#define NUM_EDGES   16384
#define NUM_NODES   100000
#define NTHREADS    128
#define WARPS_CTA   (NTHREADS / 32)

#define CONV_GROUPS (NUM_NODES * EMBED_DIM / 16)  // 1,600,000 groups of 16 floats
#define CONV_BLOCKS (CONV_GROUPS / 256)           // 6,250

// fp16 shadow of the embedding table (51.2 MB) — sanctioned __device__ scratch.
__device__ __half g_emb_h[(size_t)NUM_NODES * EMBED_DIM];
// g_offs[e] = lower_bound(seg, e); g_offs[NUM_EDGES] = total.
__device__ int g_offs[NUM_EDGES + 1];

__device__ __forceinline__ unsigned h2_bits(__half2 h)
{
    unsigned u;
    *reinterpret_cast<__half2*>(&u) = h;
    return u;
}

// Fused prepass: blocks [0, CONV_BLOCKS) convert fp32 -> fp16 (64B per thread,
// 4 independent 128-bit loads in flight); remaining blocks fill segment bounds.
__global__ void __launch_bounds__(256)
prep_kernel(const float* __restrict__ emb, const int* __restrict__ seg, int total)
{
    const int b = blockIdx.x;
    if (b < CONV_BLOCKS) {
        const size_t i = (size_t)b * 256 + threadIdx.x;   // group of 16 floats
        const float4* src = (const float4*)emb + 4 * i;
        float4 a0 = __ldcs(src + 0);
        float4 a1 = __ldcs(src + 1);
        float4 a2 = __ldcs(src + 2);
        float4 a3 = __ldcs(src + 3);
        uint4 o0, o1;
        o0.x = h2_bits(__floats2half2_rn(a0.x, a0.y));
        o0.y = h2_bits(__floats2half2_rn(a0.z, a0.w));
        o0.z = h2_bits(__floats2half2_rn(a1.x, a1.y));
        o0.w = h2_bits(__floats2half2_rn(a1.z, a1.w));
        o1.x = h2_bits(__floats2half2_rn(a2.x, a2.y));
        o1.y = h2_bits(__floats2half2_rn(a2.z, a2.w));
        o1.z = h2_bits(__floats2half2_rn(a3.x, a3.y));
        o1.w = h2_bits(__floats2half2_rn(a3.z, a3.w));
        ((uint4*)g_emb_h)[2 * i]     = o0;
        ((uint4*)g_emb_h)[2 * i + 1] = o1;
    } else {
        const int i = (b - CONV_BLOCKS) * 256 + threadIdx.x;
        if (i >= total) return;
        int cur = seg[i];
        if (i == 0) {
            for (int e = 0; e <= cur; e++) g_offs[e] = 0;
        } else {
            int prev = seg[i - 1];
            for (int e = prev + 1; e <= cur; e++) g_offs[e] = i;
        }
        if (i == total - 1) {
            for (int e = cur + 1; e <= NUM_EDGES; e++) g_offs[e] = total;
        }
    }
}

// 32-byte gather with L2 evict_last (keep the 51MB fp16 table L2-resident).
__device__ __forceinline__ ulonglong4 ldg_el8(const ulonglong4* p)
{
    ulonglong4 v;
    asm volatile("ld.global.nc.L2::evict_last.v4.b64 {%0,%1,%2,%3}, [%4];"
                 : "=l"(v.x), "=l"(v.y), "=l"(v.z), "=l"(v.w)
                 : "l"(p));
    return v;
}

__device__ __forceinline__ int ldg_cs(const int* p)
{
    int v;
    asm volatile("ld.global.cs.b32 %0, [%1];" : "=r"(v) : "l"(p));
    return v;
}

__device__ __forceinline__ void stg_cs8(ulonglong4* p, const ulonglong4 v)
{
    asm volatile("st.global.cs.v4.b64 [%0], {%1,%2,%3,%4};"
                 :: "l"(p), "l"(v.x), "l"(v.y), "l"(v.z), "l"(v.w));
}

// Accumulate 16 fp16 values (one 32B chunk) into 8 packed f32x2 accumulators.
// add.rn.f32x2 (Blackwell) halves the add instruction count.
__device__ __forceinline__ void acch2(unsigned long long* a, const ulonglong4 v)
{
    const __half2* h = (const __half2*)&v;
#pragma unroll
    for (int k = 0; k < 8; k++) {
        float2 f = __half22float2(h[k]);
        unsigned long long p;
        asm("mov.b64 %0, {%1,%2};" : "=l"(p) : "f"(f.x), "f"(f.y));
        asm("add.rn.f32x2 %0, %0, %1;" : "+l"(a[k]) : "l"(p));
    }
}

// One WARP per hyperedge on the fp16 table. fp16 row = 512B = 16 x 32B chunks,
// so one 256-bit load covers TWO members per warp instruction:
//   s = lane>>4 selects member of the pair, c = lane&15 selects the chunk.
// Packed f32x2 accumulation; halves combined via shfl.xor(16) at the end.
__global__ void __launch_bounds__(NTHREADS)
agg_kernel(const int* __restrict__ nidx,   // [TOTAL]
           float*     __restrict__ out)    // [NUM_EDGES, 256]
{
    const int lane = threadIdx.x & 31;
    const int e    = blockIdx.x * WARPS_CTA + (threadIdx.x >> 5);
    const int s    = lane >> 4;
    const int c    = lane & 15;

    const int lo = g_offs[e];
    const int hi = g_offs[e + 1];

    const ulonglong4* __restrict__ rows = (const ulonglong4*)g_emb_h; // 16 chunks/row

    unsigned long long acc[8];
#pragma unroll
    for (int k = 0; k < 8; k++) acc[k] = 0ull;

    // Pipelined index loads: prefetch next chunk while gathering current.
    int myidx = 0;
    if (lo + lane < hi) myidx = ldg_cs(nidx + lo + lane);

    for (int base = lo; base < hi; base += 32) {
        const int cnt = min(32, hi - base);
        const int cur = myidx;
        if (base + 32 + lane < hi) myidx = ldg_cs(nidx + base + 32 + lane);

        int j = 0;
        // 12 members (6 pairs) per iteration -> 6 independent 32B gathers/lane.
        for (; j + 11 < cnt; j += 12) {
            const int n0 = __shfl_sync(0xffffffffu, cur, j + s);
            const int n1 = __shfl_sync(0xffffffffu, cur, j + 2 + s);
            const int n2 = __shfl_sync(0xffffffffu, cur, j + 4 + s);
            const int n3 = __shfl_sync(0xffffffffu, cur, j + 6 + s);
            const int n4 = __shfl_sync(0xffffffffu, cur, j + 8 + s);
            const int n5 = __shfl_sync(0xffffffffu, cur, j + 10 + s);
            ulonglong4 v0 = ldg_el8(rows + (size_t)n0 * 16 + c);
            ulonglong4 v1 = ldg_el8(rows + (size_t)n1 * 16 + c);
            ulonglong4 v2 = ldg_el8(rows + (size_t)n2 * 16 + c);
            ulonglong4 v3 = ldg_el8(rows + (size_t)n3 * 16 + c);
            ulonglong4 v4 = ldg_el8(rows + (size_t)n4 * 16 + c);
            ulonglong4 v5 = ldg_el8(rows + (size_t)n5 * 16 + c);
            acch2(acc, v0);
            acch2(acc, v1);
            acch2(acc, v2);
            acch2(acc, v3);
            acch2(acc, v4);
            acch2(acc, v5);
        }
        for (; j + 1 < cnt; j += 2) {
            const int n = __shfl_sync(0xffffffffu, cur, j + s);
            acch2(acc, ldg_el8(rows + (size_t)n * 16 + c));
        }
        if (j < cnt) {  // odd tail: only the s==0 half-warp contributes
            const int n = __shfl_sync(0xffffffffu, cur, j);
            if (s == 0) acch2(acc, ldg_el8(rows + (size_t)n * 16 + c));
        }
    }

    // Unpack, combine the two member-pair halves, scale by 1/count.
    float accf[16];
#pragma unroll
    for (int k = 0; k < 8; k++) {
        float x, y;
        asm("mov.b64 {%0,%1}, %2;" : "=f"(x), "=f"(y) : "l"(acc[k]));
        accf[2 * k]     = x;
        accf[2 * k + 1] = y;
    }
#pragma unroll
    for (int k = 0; k < 16; k++)
        accf[k] += __shfl_xor_sync(0xffffffffu, accf[k], 16);

    const int cnt = hi - lo;
    const float inv = 1.0f / (float)(cnt > 0 ? cnt : 1);
#pragma unroll
    for (int k = 0; k < 16; k++) accf[k] *= inv;

    // Lanes 0..15 each own fp32 columns [16c, 16c+16) = output chunks 2c, 2c+1.
    if (s == 0) {
        ulonglong4 r0, r1;
        float* f0 = (float*)&r0;
        float* f1 = (float*)&r1;
#pragma unroll
        for (int k = 0; k < 8; k++) { f0[k] = accf[k]; f1[k] = accf[8 + k]; }
        ulonglong4* o = (ulonglong4*)out + (size_t)e * 32 + 2 * c;
        stg_cs8(o,     r0);
        stg_cs8(o + 1, r1);
    }
}

extern "C" void kernel_launch(void* const* d_in, const int* in_sizes, int n_in,
                              void* d_out, int out_size)
{
    const float* emb  = (const float*)d_in[0];
    const int*   nidx = (const int*)d_in[1];
    const int*   seg  = (const int*)d_in[2];
    float*       out  = (float*)d_out;
    const int total = in_sizes[1];

    const int bounds_blocks = (total + 255) / 256;
    prep_kernel<<<CONV_BLOCKS + bounds_blocks, 256>>>(emb, seg, total);
    agg_kernel<<<NUM_EDGES / WARPS_CTA, NTHREADS>>>(nidx, out);
}

// round 11
// speedup vs baseline: 1.1388x; 1.1388x over previous
#include <cuda_runtime.h>
#include <cuda_fp16.h>

#define EMBED_DIM   256
#define NUM_EDGES   16384
#define NUM_NODES   100000
#define NTHREADS    128
#define WARPS_CTA   (NTHREADS / 32)

#define CONV_GROUPS (NUM_NODES * EMBED_DIM / 8)   // 3,200,000 groups of 8 floats
#define CONV_BLOCKS (CONV_GROUPS / 256)           // 12,500

// fp16 shadow of the embedding table (51.2 MB) — sanctioned __device__ scratch.
__device__ __half g_emb_h[(size_t)NUM_NODES * EMBED_DIM];
// g_offs[e] = lower_bound(seg, e); g_offs[NUM_EDGES] = total.
__device__ int g_offs[NUM_EDGES + 1];

__device__ __forceinline__ unsigned h2_bits(__half2 h)
{
    unsigned u;
    *reinterpret_cast<__half2*>(&u) = h;
    return u;
}

// Fused prepass (R9-measured-best config): blocks [0, CONV_BLOCKS) convert
// fp32 -> fp16 at 8 floats/thread; remaining blocks fill segment bounds.
__global__ void __launch_bounds__(256)
prep_kernel(const float* __restrict__ emb, const int* __restrict__ seg, int total)
{
    const int b = blockIdx.x;
    if (b < CONV_BLOCKS) {
        const int i = b * 256 + threadIdx.x;           // group of 8 floats
        const float4* src = (const float4*)emb;
        float4 a = __ldcs(src + 2 * (size_t)i);
        float4 c = __ldcs(src + 2 * (size_t)i + 1);
        uint4 o;
        o.x = h2_bits(__floats2half2_rn(a.x, a.y));
        o.y = h2_bits(__floats2half2_rn(a.z, a.w));
        o.z = h2_bits(__floats2half2_rn(c.x, c.y));
        o.w = h2_bits(__floats2half2_rn(c.z, c.w));
        ((uint4*)g_emb_h)[i] = o;
    } else {
        const int i = (b - CONV_BLOCKS) * 256 + threadIdx.x;
        if (i >= total) return;
        int cur = seg[i];
        if (i == 0) {
            for (int e = 0; e <= cur; e++) g_offs[e] = 0;
        } else {
            int prev = seg[i - 1];
            for (int e = prev + 1; e <= cur; e++) g_offs[e] = i;
        }
        if (i == total - 1) {
            for (int e = cur + 1; e <= NUM_EDGES; e++) g_offs[e] = total;
        }
    }
}

// 16-byte gather (non-volatile: let ptxas batch/hoist).
__device__ __forceinline__ ulonglong2 ldg16(const ulonglong2* p)
{
    ulonglong2 v;
    asm("ld.global.nc.v2.b64 {%0,%1}, [%2];"
        : "=l"(v.x), "=l"(v.y) : "l"(p));
    return v;
}

__device__ __forceinline__ int ldg_cs(const int* p)
{
    int v;
    asm volatile("ld.global.cs.b32 %0, [%1];" : "=r"(v) : "l"(p));
    return v;
}

__device__ __forceinline__ void stg_cs8(ulonglong4* p, const ulonglong4 v)
{
    asm volatile("st.global.cs.v4.b64 [%0], {%1,%2,%3,%4};"
                 :: "l"(p), "l"(v.x), "l"(v.y), "l"(v.z), "l"(v.w));
}

// Accumulate 8 fp16 values (one 16B chunk) into fp32 accumulators.
__device__ __forceinline__ void acch(float* a, const ulonglong2 v)
{
    const __half2* h = (const __half2*)&v;
#pragma unroll
    for (int k = 0; k < 4; k++) {
        float2 f = __half22float2(h[k]);
        a[2 * k]     += f.x;
        a[2 * k + 1] += f.y;
    }
}

// One WARP per hyperedge on the fp16 table. fp16 row = 512B = 32 x 16B chunks:
// lane c owns chunk c (= 8 fp32 output columns). One warp load per member row;
// 8-member unroll puts 8 INDEPENDENT row addresses in flight per lane.
__global__ void __launch_bounds__(NTHREADS)
agg_kernel(const int* __restrict__ nidx,   // [TOTAL]
           float*     __restrict__ out)    // [NUM_EDGES, 256]
{
    const int lane = threadIdx.x & 31;
    const int e    = blockIdx.x * WARPS_CTA + (threadIdx.x >> 5);

    const int lo = g_offs[e];
    const int hi = g_offs[e + 1];

    const ulonglong2* __restrict__ rows = (const ulonglong2*)g_emb_h; // 32 chunks/row

    float acc[8];
#pragma unroll
    for (int k = 0; k < 8; k++) acc[k] = 0.0f;

    // Pipelined index loads: prefetch next chunk while gathering current.
    int myidx = 0;
    if (lo + lane < hi) myidx = ldg_cs(nidx + lo + lane);

    for (int base = lo; base < hi; base += 32) {
        const int cnt = min(32, hi - base);
        const int cur = myidx;
        if (base + 32 + lane < hi) myidx = ldg_cs(nidx + base + 32 + lane);

        int j = 0;
        // 8 members per iteration -> 8 independent 16B gathers in flight/lane.
        for (; j + 7 < cnt; j += 8) {
            const int n0 = __shfl_sync(0xffffffffu, cur, j);
            const int n1 = __shfl_sync(0xffffffffu, cur, j + 1);
            const int n2 = __shfl_sync(0xffffffffu, cur, j + 2);
            const int n3 = __shfl_sync(0xffffffffu, cur, j + 3);
            const int n4 = __shfl_sync(0xffffffffu, cur, j + 4);
            const int n5 = __shfl_sync(0xffffffffu, cur, j + 5);
            const int n6 = __shfl_sync(0xffffffffu, cur, j + 6);
            const int n7 = __shfl_sync(0xffffffffu, cur, j + 7);
            ulonglong2 v0 = ldg16(rows + (size_t)n0 * 32 + lane);
            ulonglong2 v1 = ldg16(rows + (size_t)n1 * 32 + lane);
            ulonglong2 v2 = ldg16(rows + (size_t)n2 * 32 + lane);
            ulonglong2 v3 = ldg16(rows + (size_t)n3 * 32 + lane);
            ulonglong2 v4 = ldg16(rows + (size_t)n4 * 32 + lane);
            ulonglong2 v5 = ldg16(rows + (size_t)n5 * 32 + lane);
            ulonglong2 v6 = ldg16(rows + (size_t)n6 * 32 + lane);
            ulonglong2 v7 = ldg16(rows + (size_t)n7 * 32 + lane);
            acch(acc, v0); acch(acc, v1); acch(acc, v2); acch(acc, v3);
            acch(acc, v4); acch(acc, v5); acch(acc, v6); acch(acc, v7);
        }
        for (; j < cnt; j++) {
            const int n = __shfl_sync(0xffffffffu, cur, j);
            acch(acc, ldg16(rows + (size_t)n * 32 + lane));
        }
    }

    const int cnt = hi - lo;
    const float inv = 1.0f / (float)(cnt > 0 ? cnt : 1);
#pragma unroll
    for (int k = 0; k < 8; k++) acc[k] *= inv;

    // Lane c owns fp32 columns [8c, 8c+8) -> one 32B store.
    ulonglong4 r;
    float* f = (float*)&r;
#pragma unroll
    for (int k = 0; k < 8; k++) f[k] = acc[k];
    stg_cs8((ulonglong4*)out + (size_t)e * 32 + lane, r);
}

extern "C" void kernel_launch(void* const* d_in, const int* in_sizes, int n_in,
                              void* d_out, int out_size)
{
    const float* emb  = (const float*)d_in[0];
    const int*   nidx = (const int*)d_in[1];
    const int*   seg  = (const int*)d_in[2];
    float*       out  = (float*)d_out;
    const int total = in_sizes[1];

    const int bounds_blocks = (total + 255) / 256;
    prep_kernel<<<CONV_BLOCKS + bounds_blocks, 256>>>(emb, seg, total);
    agg_kernel<<<NUM_EDGES / WARPS_CTA, NTHREADS>>>(nidx, out);
}